// round 2
// baseline (speedup 1.0000x reference)
#include <cuda_runtime.h>

#define N_NODES 100000
#define N_EDGES 1600000
#define F 128
#define NCLS 64

// ---------------- scratch (no allocation allowed; __device__ globals) ------
__device__ float g_bufA[(size_t)N_NODES * F];   // agg output (norm-scaled)
__device__ float g_bufB[(size_t)N_NODES * F];   // hidden activations
__device__ int   g_counts[N_NODES];
__device__ int   g_rowstart[N_NODES + 1];
__device__ int   g_cursor[N_NODES];
__device__ int   g_eidx[N_EDGES];
__device__ int   g_blocksums[128];

// ---------------- CSR build -----------------------------------------------
__global__ void k_zero_counts() {
    int i = blockIdx.x * blockDim.x + threadIdx.x;
    if (i < N_NODES) g_counts[i] = 0;
}

__global__ void k_hist(const int* __restrict__ dst) {
    int e = blockIdx.x * blockDim.x + threadIdx.x;
    if (e < N_EDGES) atomicAdd(&g_counts[dst[e]], 1);
}

// block-level Hillis-Steele scan, 1024 elems/block
__global__ void k_scan1() {
    __shared__ int s[1024];
    int t = threadIdx.x;
    int i = blockIdx.x * 1024 + t;
    int v = (i < N_NODES) ? g_counts[i] : 0;
    s[t] = v;
    __syncthreads();
    for (int off = 1; off < 1024; off <<= 1) {
        int x = (t >= off) ? s[t - off] : 0;
        __syncthreads();
        s[t] += x;
        __syncthreads();
    }
    if (i < N_NODES) g_rowstart[i] = s[t] - v;   // exclusive
    if (t == 1023) g_blocksums[blockIdx.x] = s[1023];
}

__global__ void k_scan2(int nblocks) {
    __shared__ int s[128];
    int t = threadIdx.x;
    int v = (t < nblocks) ? g_blocksums[t] : 0;
    s[t] = v;
    __syncthreads();
    for (int off = 1; off < 128; off <<= 1) {
        int x = (t >= off) ? s[t - off] : 0;
        __syncthreads();
        s[t] += x;
        __syncthreads();
    }
    if (t < nblocks) g_blocksums[t] = s[t] - v;  // exclusive
}

__global__ void k_scan3() {
    int i = blockIdx.x * blockDim.x + threadIdx.x;
    if (i < N_NODES) {
        int r = g_rowstart[i] + g_blocksums[i >> 10];
        g_rowstart[i] = r;
        g_cursor[i]   = r;
    }
    if (i == N_NODES) g_rowstart[N_NODES] = N_EDGES;
}

__global__ void k_scatter(const int* __restrict__ src, const int* __restrict__ dst) {
    int e = blockIdx.x * blockDim.x + threadIdx.x;
    if (e < N_EDGES) {
        int p = atomicAdd(&g_cursor[dst[e]], 1);
        g_eidx[p] = src[e];
    }
}

// ---------------- aggregation: warp per node, lane = float4 chunk ---------
// out[node] = norm[node] * sum_{e in in(node)} h[src(e)]
__global__ void k_agg(const float* __restrict__ h, const float* __restrict__ norm,
                      float* __restrict__ out) {
    int w = (blockIdx.x * blockDim.x + threadIdx.x) >> 5;
    int lane = threadIdx.x & 31;
    if (w >= N_NODES) return;
    int beg = g_rowstart[w];
    int end = g_rowstart[w + 1];

    float ax = 0.f, ay = 0.f, az = 0.f, aw = 0.f;
    int e = beg;
    // 4-way unroll for MLP (independent L2 gathers in flight)
    for (; e + 4 <= end; e += 4) {
        int s0 = g_eidx[e + 0];
        int s1 = g_eidx[e + 1];
        int s2 = g_eidx[e + 2];
        int s3 = g_eidx[e + 3];
        float4 v0 = *(const float4*)(h + (size_t)s0 * F + lane * 4);
        float4 v1 = *(const float4*)(h + (size_t)s1 * F + lane * 4);
        float4 v2 = *(const float4*)(h + (size_t)s2 * F + lane * 4);
        float4 v3 = *(const float4*)(h + (size_t)s3 * F + lane * 4);
        ax += v0.x + v1.x + v2.x + v3.x;
        ay += v0.y + v1.y + v2.y + v3.y;
        az += v0.z + v1.z + v2.z + v3.z;
        aw += v0.w + v1.w + v2.w + v3.w;
    }
    for (; e < end; ++e) {
        int s = g_eidx[e];
        float4 v = *(const float4*)(h + (size_t)s * F + lane * 4);
        ax += v.x; ay += v.y; az += v.z; aw += v.w;
    }
    float nf = norm[w];
    float4 r = make_float4(ax * nf, ay * nf, az * nf, aw * nf);
    *(float4*)(out + (size_t)w * F + lane * 4) = r;
}

// ---------------- GEMM: C[M,NOUT] = A[M,128] @ W[128,NOUT] + b (opt relu) --
// Tile: 128 rows/block, full K=128, full NOUT. 256 threads, 8xTN per thread.
template<int NOUT, bool RELU>
__global__ void k_gemm(const float* __restrict__ A, const float* __restrict__ W,
                       const float* __restrict__ bias, float* __restrict__ C) {
    constexpr int TN = NOUT / 16;          // 8 for 128, 4 for 64
    extern __shared__ float smem[];
    float* As = smem;                      // [128][132] padded
    float* Ws = smem + 128 * 132;          // [128][NOUT]

    int tid = threadIdx.x;                 // 256 threads
    int m0 = blockIdx.x * 128;

    // load W tile (whole W)
    for (int i = tid * 4; i < 128 * NOUT; i += 256 * 4)
        *(float4*)&Ws[i] = *(const float4*)&W[i];

    // load A tile (row-major, pad stride 132)
    for (int idx = tid; idx < 128 * 32; idx += 256) {
        int m = idx >> 5, kq = idx & 31;
        float4 v = make_float4(0.f, 0.f, 0.f, 0.f);
        if (m0 + m < N_NODES)
            v = *(const float4*)&A[(size_t)(m0 + m) * 128 + kq * 4];
        *(float4*)&As[m * 132 + kq * 4] = v;
    }
    __syncthreads();

    int ty = tid >> 4, tx = tid & 15;      // 16x16 thread grid
    int rm = ty * 8;
    int cn = tx * TN;

    float acc[8][TN];
#pragma unroll
    for (int r = 0; r < 8; ++r)
#pragma unroll
        for (int c = 0; c < TN; ++c) acc[r][c] = 0.f;

#pragma unroll 4
    for (int k = 0; k < 128; ++k) {
        float a[8];
#pragma unroll
        for (int r = 0; r < 8; ++r) a[r] = As[(rm + r) * 132 + k];
        float w[TN];
#pragma unroll
        for (int c = 0; c < TN; c += 4)
            *(float4*)&w[c] = *(float4*)&Ws[k * NOUT + cn + c];
#pragma unroll
        for (int r = 0; r < 8; ++r)
#pragma unroll
            for (int c = 0; c < TN; ++c)
                acc[r][c] = fmaf(a[r], w[c], acc[r][c]);
    }

    float bv[TN];
#pragma unroll
    for (int c = 0; c < TN; c += 4)
        *(float4*)&bv[c] = *(const float4*)&bias[cn + c];

#pragma unroll
    for (int r = 0; r < 8; ++r) {
        int m = m0 + rm + r;
        if (m < N_NODES) {
#pragma unroll
            for (int c = 0; c < TN; ++c) {
                float o = acc[r][c] + bv[c];
                if (RELU) o = fmaxf(o, 0.f);
                acc[r][c] = o;
            }
#pragma unroll
            for (int c = 0; c < TN; c += 4)
                *(float4*)&C[(size_t)m * NOUT + cn + c] = *(float4*)&acc[r][c];
        }
    }
}

// ---------------- launch ---------------------------------------------------
extern "C" void kernel_launch(void* const* d_in, const int* in_sizes, int n_in,
                              void* d_out, int out_size) {
    const float* features = (const float*)d_in[0];
    const float* norm     = (const float*)d_in[1];
    const float* W0       = (const float*)d_in[2];
    const float* b0       = (const float*)d_in[3];
    const float* W1       = (const float*)d_in[4];
    const float* b1       = (const float*)d_in[5];
    const float* W2       = (const float*)d_in[6];
    const float* b2       = (const float*)d_in[7];
    const int*   src      = (const int*)d_in[8];
    const int*   dst      = (const int*)d_in[9];
    float* out = (float*)d_out;

    float *bufA = nullptr, *bufB = nullptr;
    cudaGetSymbolAddress((void**)&bufA, g_bufA);
    cudaGetSymbolAddress((void**)&bufB, g_bufB);

    const int SM128 = 128 * 132 * 4 + 128 * 128 * 4;  // 133120 B
    const int SM64  = 128 * 132 * 4 + 128 * 64  * 4;  // 100352 B
    cudaFuncSetAttribute(k_gemm<128, true>,  cudaFuncAttributeMaxDynamicSharedMemorySize, SM128);
    cudaFuncSetAttribute(k_gemm<64,  false>, cudaFuncAttributeMaxDynamicSharedMemorySize, SM64);

    // CSR build (by dst)
    k_zero_counts<<<(N_NODES + 255) / 256, 256>>>();
    k_hist<<<(N_EDGES + 255) / 256, 256>>>(dst);
    int nb = (N_NODES + 1023) / 1024;   // 98
    k_scan1<<<nb, 1024>>>();
    k_scan2<<<1, 128>>>(nb);
    k_scan3<<<(N_NODES + 1 + 255) / 256, 256>>>();
    k_scatter<<<(N_EDGES + 255) / 256, 256>>>(src, dst);

    dim3 aggGrid((N_NODES + 7) / 8);    // 8 warps/block of 256 threads
    int gemmGrid = (N_NODES + 127) / 128;

    // layer 0
    k_agg<<<aggGrid, 256>>>(features, norm, bufA);
    k_gemm<128, true><<<gemmGrid, 256, SM128>>>(bufA, W0, b0, bufB);
    // layer 1
    k_agg<<<aggGrid, 256>>>(bufB, norm, bufA);
    k_gemm<128, true><<<gemmGrid, 256, SM128>>>(bufA, W1, b1, bufB);
    // layer 2 (no relu, 64 classes, write straight to d_out)
    k_agg<<<aggGrid, 256>>>(bufB, norm, bufA);
    k_gemm<64, false><<<gemmGrid, 256, SM64>>>(bufA, W2, b2, out);
}

// round 3
// speedup vs baseline: 1.0030x; 1.0030x over previous
#include <cuda_runtime.h>

#define N_NODES 100000
#define N_EDGES 1600000
#define F 128
#define NCLS 64

// ---------------- scratch (no allocation allowed; __device__ globals) ------
__device__ float g_bufA[(size_t)N_NODES * F];   // agg output (norm-scaled)
__device__ float g_bufB[(size_t)N_NODES * F];   // hidden activations
__device__ int   g_counts[N_NODES];
__device__ int   g_rowstart[N_NODES + 1];
__device__ int   g_cursor[N_NODES];
__device__ int   g_eidx[N_EDGES];
__device__ int   g_blocksums[128];

// ---------------- CSR build -----------------------------------------------
__global__ void k_zero_counts() {
    int i = blockIdx.x * blockDim.x + threadIdx.x;
    if (i < N_NODES) g_counts[i] = 0;
}

__global__ void k_hist(const int* __restrict__ dst) {
    int e = blockIdx.x * blockDim.x + threadIdx.x;
    if (e < N_EDGES) atomicAdd(&g_counts[dst[e]], 1);
}

// block-level Hillis-Steele scan, 1024 elems/block
__global__ void k_scan1() {
    __shared__ int s[1024];
    int t = threadIdx.x;
    int i = blockIdx.x * 1024 + t;
    int v = (i < N_NODES) ? g_counts[i] : 0;
    s[t] = v;
    __syncthreads();
    for (int off = 1; off < 1024; off <<= 1) {
        int x = (t >= off) ? s[t - off] : 0;
        __syncthreads();
        s[t] += x;
        __syncthreads();
    }
    if (i < N_NODES) g_rowstart[i] = s[t] - v;   // exclusive
    if (t == 1023) g_blocksums[blockIdx.x] = s[1023];
}

__global__ void k_scan2(int nblocks) {
    __shared__ int s[128];
    int t = threadIdx.x;
    int v = (t < nblocks) ? g_blocksums[t] : 0;
    s[t] = v;
    __syncthreads();
    for (int off = 1; off < 128; off <<= 1) {
        int x = (t >= off) ? s[t - off] : 0;
        __syncthreads();
        s[t] += x;
        __syncthreads();
    }
    if (t < nblocks) g_blocksums[t] = s[t] - v;  // exclusive
}

__global__ void k_scan3() {
    int i = blockIdx.x * blockDim.x + threadIdx.x;
    if (i < N_NODES) {
        int r = g_rowstart[i] + g_blocksums[i >> 10];
        g_rowstart[i] = r;
        g_cursor[i]   = r;
    }
    if (i == N_NODES) g_rowstart[N_NODES] = N_EDGES;
}

__global__ void k_scatter(const int* __restrict__ src, const int* __restrict__ dst) {
    int e = blockIdx.x * blockDim.x + threadIdx.x;
    if (e < N_EDGES) {
        int p = atomicAdd(&g_cursor[dst[e]], 1);
        g_eidx[p] = src[e];
    }
}

// ---------------- aggregation: warp per node, lane = float4 chunk ---------
// out[node] = norm[node] * sum_{e in in(node)} h[src(e)]
__global__ void k_agg(const float* __restrict__ h, const float* __restrict__ norm,
                      float* __restrict__ out) {
    int w = (blockIdx.x * blockDim.x + threadIdx.x) >> 5;
    int lane = threadIdx.x & 31;
    if (w >= N_NODES) return;
    int beg = g_rowstart[w];
    int end = g_rowstart[w + 1];

    float ax = 0.f, ay = 0.f, az = 0.f, aw = 0.f;
    int e = beg;
    // 4-way unroll for MLP (independent L2 gathers in flight)
    for (; e + 4 <= end; e += 4) {
        int s0 = g_eidx[e + 0];
        int s1 = g_eidx[e + 1];
        int s2 = g_eidx[e + 2];
        int s3 = g_eidx[e + 3];
        float4 v0 = *(const float4*)(h + (size_t)s0 * F + lane * 4);
        float4 v1 = *(const float4*)(h + (size_t)s1 * F + lane * 4);
        float4 v2 = *(const float4*)(h + (size_t)s2 * F + lane * 4);
        float4 v3 = *(const float4*)(h + (size_t)s3 * F + lane * 4);
        ax += v0.x + v1.x + v2.x + v3.x;
        ay += v0.y + v1.y + v2.y + v3.y;
        az += v0.z + v1.z + v2.z + v3.z;
        aw += v0.w + v1.w + v2.w + v3.w;
    }
    for (; e < end; ++e) {
        int s = g_eidx[e];
        float4 v = *(const float4*)(h + (size_t)s * F + lane * 4);
        ax += v.x; ay += v.y; az += v.z; aw += v.w;
    }
    float nf = norm[w];
    float4 r = make_float4(ax * nf, ay * nf, az * nf, aw * nf);
    *(float4*)(out + (size_t)w * F + lane * 4) = r;
}

// ---------------- GEMM: C[M,NOUT] = A[M,128] @ W[128,NOUT] + b (opt relu) --
// Tile: 128 rows/block, full K=128, full NOUT. 256 threads, 8xTN per thread.
template<int NOUT, bool RELU>
__global__ void k_gemm(const float* __restrict__ A, const float* __restrict__ W,
                       const float* __restrict__ bias, float* __restrict__ C) {
    constexpr int TN = NOUT / 16;          // 8 for 128, 4 for 64
    extern __shared__ float smem[];
    float* As = smem;                      // [128][132] padded
    float* Ws = smem + 128 * 132;          // [128][NOUT]

    int tid = threadIdx.x;                 // 256 threads
    int m0 = blockIdx.x * 128;

    // load W tile (whole W)
    for (int i = tid * 4; i < 128 * NOUT; i += 256 * 4)
        *(float4*)&Ws[i] = *(const float4*)&W[i];

    // load A tile (row-major, pad stride 132)
    for (int idx = tid; idx < 128 * 32; idx += 256) {
        int m = idx >> 5, kq = idx & 31;
        float4 v = make_float4(0.f, 0.f, 0.f, 0.f);
        if (m0 + m < N_NODES)
            v = *(const float4*)&A[(size_t)(m0 + m) * 128 + kq * 4];
        *(float4*)&As[m * 132 + kq * 4] = v;
    }
    __syncthreads();

    int ty = tid >> 4, tx = tid & 15;      // 16x16 thread grid
    int rm = ty * 8;
    int cn = tx * TN;

    float acc[8][TN];
#pragma unroll
    for (int r = 0; r < 8; ++r)
#pragma unroll
        for (int c = 0; c < TN; ++c) acc[r][c] = 0.f;

#pragma unroll 4
    for (int k = 0; k < 128; ++k) {
        float a[8];
#pragma unroll
        for (int r = 0; r < 8; ++r) a[r] = As[(rm + r) * 132 + k];
        float w[TN];
#pragma unroll
        for (int c = 0; c < TN; c += 4)
            *(float4*)&w[c] = *(float4*)&Ws[k * NOUT + cn + c];
#pragma unroll
        for (int r = 0; r < 8; ++r)
#pragma unroll
            for (int c = 0; c < TN; ++c)
                acc[r][c] = fmaf(a[r], w[c], acc[r][c]);
    }

    float bv[TN];
#pragma unroll
    for (int c = 0; c < TN; c += 4)
        *(float4*)&bv[c] = *(const float4*)&bias[cn + c];

#pragma unroll
    for (int r = 0; r < 8; ++r) {
        int m = m0 + rm + r;
        if (m < N_NODES) {
#pragma unroll
            for (int c = 0; c < TN; ++c) {
                float o = acc[r][c] + bv[c];
                if (RELU) o = fmaxf(o, 0.f);
                acc[r][c] = o;
            }
#pragma unroll
            for (int c = 0; c < TN; c += 4)
                *(float4*)&C[(size_t)m * NOUT + cn + c] = *(float4*)&acc[r][c];
        }
    }
}

// ---------------- launch ---------------------------------------------------
extern "C" void kernel_launch(void* const* d_in, const int* in_sizes, int n_in,
                              void* d_out, int out_size) {
    const float* features = (const float*)d_in[0];
    const float* norm     = (const float*)d_in[1];
    const float* W0       = (const float*)d_in[2];
    const float* b0       = (const float*)d_in[3];
    const float* W1       = (const float*)d_in[4];
    const float* b1       = (const float*)d_in[5];
    const float* W2       = (const float*)d_in[6];
    const float* b2       = (const float*)d_in[7];
    const int*   src      = (const int*)d_in[8];
    const int*   dst      = (const int*)d_in[9];
    float* out = (float*)d_out;

    float *bufA = nullptr, *bufB = nullptr;
    cudaGetSymbolAddress((void**)&bufA, g_bufA);
    cudaGetSymbolAddress((void**)&bufB, g_bufB);

    const int SM128 = 128 * 132 * 4 + 128 * 128 * 4;  // 133120 B
    const int SM64  = 128 * 132 * 4 + 128 * 64  * 4;  // 100352 B
    cudaFuncSetAttribute(k_gemm<128, true>,  cudaFuncAttributeMaxDynamicSharedMemorySize, SM128);
    cudaFuncSetAttribute(k_gemm<64,  false>, cudaFuncAttributeMaxDynamicSharedMemorySize, SM64);

    // CSR build (by dst)
    k_zero_counts<<<(N_NODES + 255) / 256, 256>>>();
    k_hist<<<(N_EDGES + 255) / 256, 256>>>(dst);
    int nb = (N_NODES + 1023) / 1024;   // 98
    k_scan1<<<nb, 1024>>>();
    k_scan2<<<1, 128>>>(nb);
    k_scan3<<<(N_NODES + 1 + 255) / 256, 256>>>();
    k_scatter<<<(N_EDGES + 255) / 256, 256>>>(src, dst);

    dim3 aggGrid((N_NODES + 7) / 8);    // 8 warps/block of 256 threads
    int gemmGrid = (N_NODES + 127) / 128;

    // layer 0
    k_agg<<<aggGrid, 256>>>(features, norm, bufA);
    k_gemm<128, true><<<gemmGrid, 256, SM128>>>(bufA, W0, b0, bufB);
    // layer 1
    k_agg<<<aggGrid, 256>>>(bufB, norm, bufA);
    k_gemm<128, true><<<gemmGrid, 256, SM128>>>(bufA, W1, b1, bufB);
    // layer 2 (no relu, 64 classes, write straight to d_out)
    k_agg<<<aggGrid, 256>>>(bufB, norm, bufA);
    k_gemm<64, false><<<gemmGrid, 256, SM64>>>(bufA, W2, b2, out);
}